// round 14
// baseline (speedup 1.0000x reference)
#include <cuda_runtime.h>
#include <cuda_bf16.h>
#include <math.h>
#include <stdint.h>

// Problem constants
#define Bb 4
#define Tt 2048
#define Hh 16
#define Dd 64
#define Cc 1024

// Scratch (__device__ globals per allocation rules)
__device__ __nv_bfloat16 g_qkvhi[Bb * Tt * 3 * Cc];
__device__ __nv_bfloat16 g_qkvlo[Bb * Tt * 3 * Cc];
__device__ __nv_bfloat16 g_xhi[Bb * Tt * Cc];
__device__ __nv_bfloat16 g_xlo[Bb * Tt * Cc];
__device__ __nv_bfloat16 g_wqhi[Cc * 3 * Cc];
__device__ __nv_bfloat16 g_wqlo[Cc * 3 * Cc];
__device__ __nv_bfloat16 g_wohi[Cc * Cc];
__device__ __nv_bfloat16 g_wolo[Cc * Cc];
__device__ __nv_bfloat16 g_ahi[Bb * Tt * Cc];
__device__ __nv_bfloat16 g_alo[Bb * Tt * Cc];

// ---------------------------------------------------------------------------
// PTX helpers
// ---------------------------------------------------------------------------
__device__ __forceinline__ uint32_t smem_u32(const void* p) {
    uint32_t a;
    asm("{ .reg .u64 t; cvta.to.shared.u64 t, %1; cvt.u32.u64 %0, t; }"
        : "=r"(a) : "l"(p));
    return a;
}

#define CP16(dst, src) \
    asm volatile("cp.async.cg.shared.global [%0], [%1], 16;" \
        :: "r"(dst), "l"(src) : "memory")
#define CP_COMMIT() asm volatile("cp.async.commit_group;" ::: "memory")
#define CP_WAIT1()  asm volatile("cp.async.wait_group 1;" ::: "memory")
#define CP_WAIT0()  asm volatile("cp.async.wait_group 0;" ::: "memory")

#define LDSM4(r, addr) \
    asm volatile("ldmatrix.sync.aligned.m8n8.x4.shared.b16 {%0,%1,%2,%3}, [%4];" \
        : "=r"((r)[0]), "=r"((r)[1]), "=r"((r)[2]), "=r"((r)[3]) : "r"(addr))
#define LDSM4T(r, addr) \
    asm volatile("ldmatrix.sync.aligned.m8n8.x4.trans.shared.b16 {%0,%1,%2,%3}, [%4];" \
        : "=r"((r)[0]), "=r"((r)[1]), "=r"((r)[2]), "=r"((r)[3]) : "r"(addr))

#define MMA_BF16(d, a, b0, b1) \
    asm volatile("mma.sync.aligned.m16n8k16.row.col.f32.bf16.bf16.f32 " \
        "{%0,%1,%2,%3}, {%4,%5,%6,%7}, {%8,%9}, {%0,%1,%2,%3};" \
        : "+f"((d)[0]), "+f"((d)[1]), "+f"((d)[2]), "+f"((d)[3]) \
        : "r"((a)[0]), "r"((a)[1]), "r"((a)[2]), "r"((a)[3]), "r"(b0), "r"(b1))

// ---------------------------------------------------------------------------
// Fused split: one launch covers x (8M), w_qkv (3M), w_out (1M) elements.
// ---------------------------------------------------------------------------
#define NX (Bb * Tt * Cc)          // 8388608
#define NW (Cc * 3 * Cc)           // 3145728
#define NO (Cc * Cc)               // 1048576

__global__ __launch_bounds__(256) void split3_kernel(
    const float* __restrict__ x, const float* __restrict__ wq,
    const float* __restrict__ wo,
    __nv_bfloat16* __restrict__ xhi, __nv_bfloat16* __restrict__ xlo,
    __nv_bfloat16* __restrict__ wqhi, __nv_bfloat16* __restrict__ wqlo,
    __nv_bfloat16* __restrict__ wohi, __nv_bfloat16* __restrict__ wolo)
{
    long long i = ((long long)blockIdx.x * 256 + threadIdx.x) * 4;
    const float* in;
    __nv_bfloat16 *hi, *lo;
    if (i < NX)                { in = x;  hi = xhi;  lo = xlo; }
    else if (i < NX + NW)      { in = wq; hi = wqhi; lo = wqlo; i -= NX; }
    else if (i < NX + NW + NO) { in = wo; hi = wohi; lo = wolo; i -= NX + NW; }
    else return;

    float4 v = *(const float4*)(in + i);
    __nv_bfloat16 h[4], l[4];
    float xx[4] = {v.x, v.y, v.z, v.w};
#pragma unroll
    for (int j = 0; j < 4; j++) {
        h[j] = __float2bfloat16(xx[j]);
        l[j] = __float2bfloat16(xx[j] - __bfloat162float(h[j]));
    }
    *(uint64_t*)(hi + i) = *(uint64_t*)h;
    *(uint64_t*)(lo + i) = *(uint64_t*)l;
}

// ---------------------------------------------------------------------------
// 3xBF16 split GEMM. 256x128 CTA tile (M doubled to cut LDGSTS ops per HMMA
// by 25%), BK=32, 256 threads (8 warps, 4x2 grid, 64x64 warp tile), 3-stage
// cp.async ring, 1 CTA/SM. Term-outer MMA order.
// ---------------------------------------------------------------------------
#define GK 1024
#define ASTRIDE 80
#define BSTRIDE 272
#define GM 256
#define ATILE (GM * ASTRIDE)            // 20480
#define BTILE (32 * BSTRIDE)            // 8704
#define BUFBYTES (2 * ATILE + 2 * BTILE) // 58368
#define GSTAGES 3
#define GSMEM (GSTAGES * BUFBYTES)       // 175104

__device__ __forceinline__ void gemm_issue(
    int c, uint32_t buf, int tid, int bm, int bn, int N,
    const __nv_bfloat16* __restrict__ Ahi, const __nv_bfloat16* __restrict__ Alo,
    const __nv_bfloat16* __restrict__ Bhi, const __nv_bfloat16* __restrict__ Blo)
{
    // A tiles: 256 rows x 4 chunks of 16B, 256 threads x 4 iters (hi+lo)
#pragma unroll
    for (int i = 0; i < 4; i++) {
        int idx = tid + 256 * i;
        int row = idx >> 2, c4 = idx & 3;
        size_t aoff = (size_t)(bm + row) * GK + c * 32 + c4 * 8;
        CP16(buf + row * ASTRIDE + c4 * 16, Ahi + aoff);
        CP16(buf + ATILE + row * ASTRIDE + c4 * 16, Alo + aoff);
    }
    // B tiles: 32 rows x 16 chunks of 16B, 256 threads x 2 iters (hi+lo)
#pragma unroll
    for (int i = 0; i < 2; i++) {
        int idx = tid + 256 * i;
        int row = idx >> 4, c16 = idx & 15;
        size_t boff = (size_t)(c * 32 + row) * N + bn + c16 * 8;
        CP16(buf + 2 * ATILE + row * BSTRIDE + c16 * 16, Bhi + boff);
        CP16(buf + 2 * ATILE + BTILE + row * BSTRIDE + c16 * 16, Blo + boff);
    }
}

template <int OUTMODE>
__global__ __launch_bounds__(256, 1) void gemm3_bf16_kernel(
    const __nv_bfloat16* __restrict__ Ahi, const __nv_bfloat16* __restrict__ Alo,
    const __nv_bfloat16* __restrict__ Bhi, const __nv_bfloat16* __restrict__ Blo,
    float* __restrict__ C,
    __nv_bfloat16* __restrict__ Chi, __nv_bfloat16* __restrict__ Clo, int N)
{
    extern __shared__ char gsm[];
    const uint32_t DATA = smem_u32(gsm);
    const int tid  = threadIdx.x;
    const int wid  = tid >> 5;
    const int lane = tid & 31;
    const int wm   = wid >> 1;     // 0..3 (64 rows each)
    const int wn   = wid & 1;      // 0..1 (64 cols each)
    const int bm = blockIdx.y * GM;
    const int bn = blockIdx.x * 128;

    float acc[4][8][4];
#pragma unroll
    for (int mt = 0; mt < 4; mt++)
#pragma unroll
        for (int nt = 0; nt < 8; nt++)
#pragma unroll
            for (int q = 0; q < 4; q++) acc[mt][nt][q] = 0.f;

    const int lr = lane & 15, lc = lane >> 4;

    gemm_issue(0, DATA, tid, bm, bn, N, Ahi, Alo, Bhi, Blo);
    CP_COMMIT();
    gemm_issue(1, DATA + BUFBYTES, tid, bm, bn, N, Ahi, Alo, Bhi, Blo);
    CP_COMMIT();

    const int NCHUNK = GK / 32;
    for (int c = 0; c < NCHUNK; c++) {
        if (c < NCHUNK - 1) { CP_WAIT1(); } else { CP_WAIT0(); }
        __syncthreads();
        if (c + 2 < NCHUNK) {
            gemm_issue(c + 2, DATA + (uint32_t)((c + 2) % GSTAGES) * BUFBYTES,
                       tid, bm, bn, N, Ahi, Alo, Bhi, Blo);
            CP_COMMIT();
        }

        const uint32_t cur = DATA + (uint32_t)(c % GSTAGES) * BUFBYTES;
#pragma unroll
        for (int ks = 0; ks < 2; ks++) {
            uint32_t ah[4][4], al[4][4], bh[4][4], bl[4][4];
#pragma unroll
            for (int mt = 0; mt < 4; mt++) {
                uint32_t aaddr = cur + (uint32_t)((wm * 64 + mt * 16 + lr) * ASTRIDE
                               + lc * 16 + ks * 32);
                LDSM4(ah[mt], aaddr);
                LDSM4(al[mt], aaddr + ATILE);
            }
#pragma unroll
            for (int np = 0; np < 4; np++) {
                uint32_t baddr = cur + 2 * ATILE
                               + (uint32_t)((ks * 16 + lr) * BSTRIDE
                               + wn * 128 + np * 32 + lc * 16);
                LDSM4T(bh[np], baddr);
                LDSM4T(bl[np], baddr + BTILE);
            }
#pragma unroll
            for (int mt = 0; mt < 4; mt++)
#pragma unroll
                for (int nt = 0; nt < 8; nt++)
                    MMA_BF16(acc[mt][nt], ah[mt],
                             bh[nt >> 1][(nt & 1) * 2], bh[nt >> 1][(nt & 1) * 2 + 1]);
#pragma unroll
            for (int mt = 0; mt < 4; mt++)
#pragma unroll
                for (int nt = 0; nt < 8; nt++)
                    MMA_BF16(acc[mt][nt], ah[mt],
                             bl[nt >> 1][(nt & 1) * 2], bl[nt >> 1][(nt & 1) * 2 + 1]);
#pragma unroll
            for (int mt = 0; mt < 4; mt++)
#pragma unroll
                for (int nt = 0; nt < 8; nt++)
                    MMA_BF16(acc[mt][nt], al[mt],
                             bh[nt >> 1][(nt & 1) * 2], bh[nt >> 1][(nt & 1) * 2 + 1]);
        }
    }

#pragma unroll
    for (int mt = 0; mt < 4; mt++) {
        int r0 = bm + wm * 64 + mt * 16 + (lane >> 2);
#pragma unroll
        for (int nt = 0; nt < 8; nt++) {
            int col = bn + wn * 64 + nt * 8 + (lane & 3) * 2;
            if (OUTMODE == 0) {
                *(float2*)(C + (size_t)r0 * N + col) =
                    make_float2(acc[mt][nt][0], acc[mt][nt][1]);
                *(float2*)(C + (size_t)(r0 + 8) * N + col) =
                    make_float2(acc[mt][nt][2], acc[mt][nt][3]);
            } else {
#pragma unroll
                for (int rr = 0; rr < 2; rr++) {
                    float v0 = acc[mt][nt][rr * 2], v1 = acc[mt][nt][rr * 2 + 1];
                    __nv_bfloat162 hp = __floats2bfloat162_rn(v0, v1);
                    __nv_bfloat162 lp = __floats2bfloat162_rn(
                        v0 - __bfloat162float(__low2bfloat16(hp)),
                        v1 - __bfloat162float(__high2bfloat16(hp)));
                    size_t off = (size_t)(r0 + rr * 8) * N + col;
                    *(uint32_t*)(Chi + off) = *(uint32_t*)&hp;
                    *(uint32_t*)(Clo + off) = *(uint32_t*)&lp;
                }
            }
        }
    }
}

// ---------------------------------------------------------------------------
// Flash attention (3xBF16) — R13 config: 8 warps, 128-q CTA, 16 rows/warp,
// heavy-CTAs-first.
// ---------------------------------------------------------------------------
#define FSTR   72
#define FTILE_B (64 * FSTR * 2)
#define FBUF_B  (4 * FTILE_B)
#define FSTAGES 3
#define FSMEM   (FSTAGES * FBUF_B)

__device__ __forceinline__ void flash_load_tile(
    uint32_t SB, int buf, int tid, int b, int h, int k0,
    const __nv_bfloat16* __restrict__ qkh, const __nv_bfloat16* __restrict__ qkl)
{
    const int row = tid >> 2;
    const int c0 = tid & 3;
    const size_t g = (size_t)(b * Tt + k0 + row) * (3 * Cc) + h * Dd;
    const __nv_bfloat16* s0 = qkh + g + Cc;
    const __nv_bfloat16* s1 = qkl + g + Cc;
    const __nv_bfloat16* s2 = qkh + g + 2 * Cc;
    const __nv_bfloat16* s3 = qkl + g + 2 * Cc;
    uint32_t d = SB + (uint32_t)buf * FBUF_B + (uint32_t)row * 144;
    CP16(d + 0 * FTILE_B + c0 * 16,       s0 + c0 * 8);
    CP16(d + 0 * FTILE_B + (c0 + 4) * 16, s0 + (c0 + 4) * 8);
    CP16(d + 1 * FTILE_B + c0 * 16,       s1 + c0 * 8);
    CP16(d + 1 * FTILE_B + (c0 + 4) * 16, s1 + (c0 + 4) * 8);
    CP16(d + 2 * FTILE_B + c0 * 16,       s2 + c0 * 8);
    CP16(d + 2 * FTILE_B + (c0 + 4) * 16, s2 + (c0 + 4) * 8);
    CP16(d + 3 * FTILE_B + c0 * 16,       s3 + c0 * 8);
    CP16(d + 3 * FTILE_B + (c0 + 4) * 16, s3 + (c0 + 4) * 8);
}

__global__ __launch_bounds__(256, 1) void flash_mma_kernel(
    const __nv_bfloat16* __restrict__ qkh, const __nv_bfloat16* __restrict__ qkl,
    __nv_bfloat16* __restrict__ ahi, __nv_bfloat16* __restrict__ alo)
{
    extern __shared__ char fsm[];
    const uint32_t SB = smem_u32(fsm);
    const int tid  = threadIdx.x;
    const int lane = tid & 31;
    const int wid  = tid >> 5;
    const int lr = lane >> 2;
    const int lq = lane & 3;
    const int qt = (int)(gridDim.x - 1 - blockIdx.x);   // heavy CTAs first
    const int h = blockIdx.y, b = blockIdx.z;
    const int q0 = qt * 128;
    const int RS = 3 * Cc;

    uint32_t qfh[4][4], qfl[4][4];
    {
        const __nv_bfloat16* qb = qkh + (size_t)(b * Tt + q0 + wid * 16) * RS + h * Dd;
        const __nv_bfloat16* ql = qkl + (size_t)(b * Tt + q0 + wid * 16) * RS + h * Dd;
#pragma unroll
        for (int s = 0; s < 4; s++) {
            int k = s * 16 + 2 * lq;
            qfh[s][0] = *(const uint32_t*)(qb + (size_t)lr * RS + k);
            qfh[s][1] = *(const uint32_t*)(qb + (size_t)(lr + 8) * RS + k);
            qfh[s][2] = *(const uint32_t*)(qb + (size_t)lr * RS + k + 8);
            qfh[s][3] = *(const uint32_t*)(qb + (size_t)(lr + 8) * RS + k + 8);
            qfl[s][0] = *(const uint32_t*)(ql + (size_t)lr * RS + k);
            qfl[s][1] = *(const uint32_t*)(ql + (size_t)(lr + 8) * RS + k);
            qfl[s][2] = *(const uint32_t*)(ql + (size_t)lr * RS + k + 8);
            qfl[s][3] = *(const uint32_t*)(ql + (size_t)(lr + 8) * RS + k + 8);
        }
    }

    float mA = -INFINITY, mB = -INFINITY, lA = 0.f, lB = 0.f;
    float o[8][4];
#pragma unroll
    for (int nt = 0; nt < 8; nt++)
#pragma unroll
        for (int q = 0; q < 4; q++) o[nt][q] = 0.f;

    const int ktmax = 2 * qt + 1;
    flash_load_tile(SB, 0, tid, b, h, 0, qkh, qkl);
    CP_COMMIT();
    flash_load_tile(SB, 1, tid, b, h, 64, qkh, qkl);
    CP_COMMIT();

    for (int kt = 0; kt <= ktmax; kt++) {
        if (kt < ktmax) { CP_WAIT1(); } else { CP_WAIT0(); }
        __syncthreads();
        if (kt + 2 <= ktmax) {
            flash_load_tile(SB, (kt + 2) % FSTAGES, tid, b, h, (kt + 2) * 64,
                            qkh, qkl);
            CP_COMMIT();
        }

        const int k0 = kt * 64;
        if (k0 <= q0 + wid * 16 + 15) {
            const uint32_t KB = SB + (uint32_t)(kt % FSTAGES) * FBUF_B;
            const uint32_t VB = KB + 2 * FTILE_B;

            float s[8][4];
#pragma unroll
            for (int nt = 0; nt < 8; nt++)
#pragma unroll
                for (int q = 0; q < 4; q++) s[nt][q] = 0.f;

#pragma unroll
            for (int sk = 0; sk < 4; sk++) {
                uint32_t bh[4][4], bl[4][4];
#pragma unroll
                for (int p = 0; p < 4; p++) {
                    uint32_t addr = KB
                        + (uint32_t)(((lane & 7) + ((lane >> 4) << 3) + p * 16) * 144
                        + ((lane >> 3) & 1) * 16 + sk * 32);
                    LDSM4(bh[p], addr);
                    LDSM4(bl[p], addr + FTILE_B);
                }
#pragma unroll
                for (int p = 0; p < 4; p++) {
                    MMA_BF16(s[2 * p],     qfh[sk], bh[p][0], bh[p][1]);
                    MMA_BF16(s[2 * p + 1], qfh[sk], bh[p][2], bh[p][3]);
                }
#pragma unroll
                for (int p = 0; p < 4; p++) {
                    MMA_BF16(s[2 * p],     qfh[sk], bl[p][0], bl[p][1]);
                    MMA_BF16(s[2 * p + 1], qfh[sk], bl[p][2], bl[p][3]);
                }
#pragma unroll
                for (int p = 0; p < 4; p++) {
                    MMA_BF16(s[2 * p],     qfl[sk], bh[p][0], bh[p][1]);
                    MMA_BF16(s[2 * p + 1], qfl[sk], bh[p][2], bh[p][3]);
                }
            }

            const int rowA = q0 + wid * 16 + lr;
#pragma unroll
            for (int nt = 0; nt < 8; nt++)
#pragma unroll
                for (int q = 0; q < 4; q++) s[nt][q] *= 0.125f;

            if (k0 + 63 >= q0 + wid * 16) {
#pragma unroll
                for (int nt = 0; nt < 8; nt++) {
                    int col = k0 + nt * 8 + 2 * lq;
                    if (col     > rowA)     s[nt][0] = -INFINITY;
                    if (col + 1 > rowA)     s[nt][1] = -INFINITY;
                    if (col     > rowA + 8) s[nt][2] = -INFINITY;
                    if (col + 1 > rowA + 8) s[nt][3] = -INFINITY;
                }
            }

            float mxA = -INFINITY, mxB = -INFINITY;
#pragma unroll
            for (int nt = 0; nt < 8; nt++) {
                mxA = fmaxf(mxA, fmaxf(s[nt][0], s[nt][1]));
                mxB = fmaxf(mxB, fmaxf(s[nt][2], s[nt][3]));
            }
            mxA = fmaxf(mxA, __shfl_xor_sync(0xffffffffu, mxA, 1));
            mxA = fmaxf(mxA, __shfl_xor_sync(0xffffffffu, mxA, 2));
            mxB = fmaxf(mxB, __shfl_xor_sync(0xffffffffu, mxB, 1));
            mxB = fmaxf(mxB, __shfl_xor_sync(0xffffffffu, mxB, 2));
            float mnA = fmaxf(mA, mxA), mnB = fmaxf(mB, mxB);
            float alphaA = __expf(mA - mnA), alphaB = __expf(mB - mnB);
            mA = mnA; mB = mnB;

            float sumA = 0.f, sumB = 0.f;
#pragma unroll
            for (int nt = 0; nt < 8; nt++) {
                s[nt][0] = __expf(s[nt][0] - mnA);
                s[nt][1] = __expf(s[nt][1] - mnA);
                s[nt][2] = __expf(s[nt][2] - mnB);
                s[nt][3] = __expf(s[nt][3] - mnB);
                sumA += s[nt][0] + s[nt][1];
                sumB += s[nt][2] + s[nt][3];
            }
            sumA += __shfl_xor_sync(0xffffffffu, sumA, 1);
            sumA += __shfl_xor_sync(0xffffffffu, sumA, 2);
            sumB += __shfl_xor_sync(0xffffffffu, sumB, 1);
            sumB += __shfl_xor_sync(0xffffffffu, sumB, 2);
            lA = lA * alphaA + sumA;
            lB = lB * alphaB + sumB;

#pragma unroll
            for (int nt = 0; nt < 8; nt++) {
                o[nt][0] *= alphaA; o[nt][1] *= alphaA;
                o[nt][2] *= alphaB; o[nt][3] *= alphaB;
            }

#pragma unroll
            for (int sk = 0; sk < 4; sk++) {
                uint32_t ph[4], pl[4];
#pragma unroll
                for (int half = 0; half < 2; half++) {
                    const float* sv = s[2 * sk + half];
#pragma unroll
                    for (int rr = 0; rr < 2; rr++) {
                        float v0 = sv[rr * 2], v1 = sv[rr * 2 + 1];
                        __nv_bfloat162 hp = __floats2bfloat162_rn(v0, v1);
                        __nv_bfloat162 lp = __floats2bfloat162_rn(
                            v0 - __bfloat162float(__low2bfloat16(hp)),
                            v1 - __bfloat162float(__high2bfloat16(hp)));
                        ph[half * 2 + rr] = *(uint32_t*)&hp;
                        pl[half * 2 + rr] = *(uint32_t*)&lp;
                    }
                }
                uint32_t bh[4][4], bl[4][4];
#pragma unroll
                for (int p = 0; p < 4; p++) {
                    uint32_t addr = VB
                        + (uint32_t)((sk * 16 + (lane & 7) + (((lane >> 3) & 1) << 3)) * 144
                        + ((lane >> 4) * 16) + p * 32);
                    LDSM4T(bh[p], addr);
                    LDSM4T(bl[p], addr + FTILE_B);
                }
#pragma unroll
                for (int p = 0; p < 4; p++) {
                    MMA_BF16(o[2 * p],     ph, bh[p][0], bh[p][1]);
                    MMA_BF16(o[2 * p + 1], ph, bh[p][2], bh[p][3]);
                }
#pragma unroll
                for (int p = 0; p < 4; p++) {
                    MMA_BF16(o[2 * p],     ph, bl[p][0], bl[p][1]);
                    MMA_BF16(o[2 * p + 1], ph, bl[p][2], bl[p][3]);
                }
#pragma unroll
                for (int p = 0; p < 4; p++) {
                    MMA_BF16(o[2 * p],     pl, bh[p][0], bh[p][1]);
                    MMA_BF16(o[2 * p + 1], pl, bh[p][2], bh[p][3]);
                }
            }
        }
    }

    const float iA = 1.f / lA, iB = 1.f / lB;
    const size_t rA = (size_t)(b * Tt + q0 + wid * 16 + lr) * Cc + h * Dd;
    const size_t rB = rA + 8 * Cc;
#pragma unroll
    for (int nt = 0; nt < 8; nt++) {
        int col = nt * 8 + 2 * lq;
        float v0 = o[nt][0] * iA, v1 = o[nt][1] * iA;
        __nv_bfloat162 hp = __floats2bfloat162_rn(v0, v1);
        __nv_bfloat162 lp = __floats2bfloat162_rn(
            v0 - __bfloat162float(__low2bfloat16(hp)),
            v1 - __bfloat162float(__high2bfloat16(hp)));
        *(uint32_t*)(ahi + rA + col) = *(uint32_t*)&hp;
        *(uint32_t*)(alo + rA + col) = *(uint32_t*)&lp;
        float v2 = o[nt][2] * iB, v3 = o[nt][3] * iB;
        __nv_bfloat162 hp2 = __floats2bfloat162_rn(v2, v3);
        __nv_bfloat162 lp2 = __floats2bfloat162_rn(
            v2 - __bfloat162float(__low2bfloat16(hp2)),
            v3 - __bfloat162float(__high2bfloat16(hp2)));
        *(uint32_t*)(ahi + rB + col) = *(uint32_t*)&hp2;
        *(uint32_t*)(alo + rB + col) = *(uint32_t*)&lp2;
    }
}

// ---------------------------------------------------------------------------
// kernel_launch
// ---------------------------------------------------------------------------
extern "C" void kernel_launch(void* const* d_in, const int* in_sizes, int n_in,
                              void* d_out, int out_size)
{
    const float* x     = (const float*)d_in[0];
    const float* w_qkv = (const float*)d_in[1];
    const float* w_out = (const float*)d_in[2];
    float* out = (float*)d_out;

    __nv_bfloat16 *qkvhi, *qkvlo, *xhi, *xlo, *wqhi, *wqlo, *wohi, *wolo, *ahi, *alo;
    cudaGetSymbolAddress((void**)&qkvhi, g_qkvhi);
    cudaGetSymbolAddress((void**)&qkvlo, g_qkvlo);
    cudaGetSymbolAddress((void**)&xhi,  g_xhi);
    cudaGetSymbolAddress((void**)&xlo,  g_xlo);
    cudaGetSymbolAddress((void**)&wqhi, g_wqhi);
    cudaGetSymbolAddress((void**)&wqlo, g_wqlo);
    cudaGetSymbolAddress((void**)&wohi, g_wohi);
    cudaGetSymbolAddress((void**)&wolo, g_wolo);
    cudaGetSymbolAddress((void**)&ahi,  g_ahi);
    cudaGetSymbolAddress((void**)&alo,  g_alo);

    const int M = Bb * Tt;

    // 0) Fused split (one launch)
    {
        long long total = (long long)NX + NW + NO;
        int blocks = (int)(total / 1024);
        split3_kernel<<<blocks, 256>>>(x, w_qkv, w_out,
                                       xhi, xlo, wqhi, wqlo, wohi, wolo);
    }

    cudaFuncSetAttribute(gemm3_bf16_kernel<0>,
                         cudaFuncAttributeMaxDynamicSharedMemorySize, GSMEM);
    cudaFuncSetAttribute(gemm3_bf16_kernel<1>,
                         cudaFuncAttributeMaxDynamicSharedMemorySize, GSMEM);
    cudaFuncSetAttribute(flash_mma_kernel,
                         cudaFuncAttributeMaxDynamicSharedMemorySize, FSMEM);

    // 1) QKV projection: 256x128 tiles
    gemm3_bf16_kernel<1><<<dim3(3 * Cc / 128, M / GM), 256, GSMEM>>>(
        xhi, xlo, wqhi, wqlo, nullptr, qkvhi, qkvlo, 3 * Cc);

    // 2) Causal flash attention
    flash_mma_kernel<<<dim3(Tt / 128, Hh, Bb), 256, FSMEM>>>(
        qkvhi, qkvlo, ahi, alo);

    // 3) Output projection: 256x128 tiles
    gemm3_bf16_kernel<0><<<dim3(Cc / 128, M / GM), 256, GSMEM>>>(
        ahi, alo, wohi, wolo, out, nullptr, nullptr, Cc);
}

// round 15
// speedup vs baseline: 1.0614x; 1.0614x over previous
#include <cuda_runtime.h>
#include <cuda_bf16.h>
#include <math.h>
#include <stdint.h>

// Problem constants
#define Bb 4
#define Tt 2048
#define Hh 16
#define Dd 64
#define Cc 1024

// Scratch (__device__ globals per allocation rules)
__device__ __nv_bfloat16 g_qkvhi[Bb * Tt * 3 * Cc];
__device__ __nv_bfloat16 g_qkvlo[Bb * Tt * 3 * Cc];
__device__ __nv_bfloat16 g_xhi[Bb * Tt * Cc];
__device__ __nv_bfloat16 g_xlo[Bb * Tt * Cc];
__device__ __nv_bfloat16 g_wqhi[Cc * 3 * Cc];
__device__ __nv_bfloat16 g_wqlo[Cc * 3 * Cc];
__device__ __nv_bfloat16 g_wohi[Cc * Cc];
__device__ __nv_bfloat16 g_wolo[Cc * Cc];
__device__ __nv_bfloat16 g_ahi[Bb * Tt * Cc];
__device__ __nv_bfloat16 g_alo[Bb * Tt * Cc];

// ---------------------------------------------------------------------------
// PTX helpers
// ---------------------------------------------------------------------------
__device__ __forceinline__ uint32_t smem_u32(const void* p) {
    uint32_t a;
    asm("{ .reg .u64 t; cvta.to.shared.u64 t, %1; cvt.u32.u64 %0, t; }"
        : "=r"(a) : "l"(p));
    return a;
}

#define CP16(dst, src) \
    asm volatile("cp.async.cg.shared.global [%0], [%1], 16;" \
        :: "r"(dst), "l"(src) : "memory")
#define CP_COMMIT() asm volatile("cp.async.commit_group;" ::: "memory")
#define CP_WAIT1()  asm volatile("cp.async.wait_group 1;" ::: "memory")
#define CP_WAIT0()  asm volatile("cp.async.wait_group 0;" ::: "memory")

#define LDSM4(r, addr) \
    asm volatile("ldmatrix.sync.aligned.m8n8.x4.shared.b16 {%0,%1,%2,%3}, [%4];" \
        : "=r"((r)[0]), "=r"((r)[1]), "=r"((r)[2]), "=r"((r)[3]) : "r"(addr))
#define LDSM4T(r, addr) \
    asm volatile("ldmatrix.sync.aligned.m8n8.x4.trans.shared.b16 {%0,%1,%2,%3}, [%4];" \
        : "=r"((r)[0]), "=r"((r)[1]), "=r"((r)[2]), "=r"((r)[3]) : "r"(addr))

#define MMA_BF16(d, a, b0, b1) \
    asm volatile("mma.sync.aligned.m16n8k16.row.col.f32.bf16.bf16.f32 " \
        "{%0,%1,%2,%3}, {%4,%5,%6,%7}, {%8,%9}, {%0,%1,%2,%3};" \
        : "+f"((d)[0]), "+f"((d)[1]), "+f"((d)[2]), "+f"((d)[3]) \
        : "r"((a)[0]), "r"((a)[1]), "r"((a)[2]), "r"((a)[3]), "r"(b0), "r"(b1))

// ---------------------------------------------------------------------------
// Fused split: one launch covers x (8M), w_qkv (3M), w_out (1M) elements.
// ---------------------------------------------------------------------------
#define NX (Bb * Tt * Cc)          // 8388608
#define NW (Cc * 3 * Cc)           // 3145728
#define NO (Cc * Cc)               // 1048576

__global__ __launch_bounds__(256) void split3_kernel(
    const float* __restrict__ x, const float* __restrict__ wq,
    const float* __restrict__ wo,
    __nv_bfloat16* __restrict__ xhi, __nv_bfloat16* __restrict__ xlo,
    __nv_bfloat16* __restrict__ wqhi, __nv_bfloat16* __restrict__ wqlo,
    __nv_bfloat16* __restrict__ wohi, __nv_bfloat16* __restrict__ wolo)
{
    long long i = ((long long)blockIdx.x * 256 + threadIdx.x) * 4;
    const float* in;
    __nv_bfloat16 *hi, *lo;
    if (i < NX)                { in = x;  hi = xhi;  lo = xlo; }
    else if (i < NX + NW)      { in = wq; hi = wqhi; lo = wqlo; i -= NX; }
    else if (i < NX + NW + NO) { in = wo; hi = wohi; lo = wolo; i -= NX + NW; }
    else return;

    float4 v = *(const float4*)(in + i);
    __nv_bfloat16 h[4], l[4];
    float xx[4] = {v.x, v.y, v.z, v.w};
#pragma unroll
    for (int j = 0; j < 4; j++) {
        h[j] = __float2bfloat16(xx[j]);
        l[j] = __float2bfloat16(xx[j] - __bfloat162float(h[j]));
    }
    *(uint64_t*)(hi + i) = *(uint64_t*)h;
    *(uint64_t*)(lo + i) = *(uint64_t*)l;
}

// ---------------------------------------------------------------------------
// 3xBF16 split GEMM — R13 config: 128x128 CTA tile, BK=32, 128 threads
// (4 warps, 2x2, 64x64 warp tile), 3-stage cp.async ring, 2 CTAs/SM.
// OUTMODE 1 additionally pre-scales the Q block (cols < Cc) by 1/8 (exact).
// ---------------------------------------------------------------------------
#define GK 1024
#define ASTRIDE 80
#define BSTRIDE 272
#define ATILE (128 * ASTRIDE)
#define BTILE (32 * BSTRIDE)
#define BUFBYTES (2 * ATILE + 2 * BTILE)
#define GSTAGES 3
#define GSMEM (GSTAGES * BUFBYTES)

__device__ __forceinline__ void gemm_issue(
    int c, uint32_t buf, int tid, int bm, int bn, int N,
    const __nv_bfloat16* __restrict__ Ahi, const __nv_bfloat16* __restrict__ Alo,
    const __nv_bfloat16* __restrict__ Bhi, const __nv_bfloat16* __restrict__ Blo)
{
#pragma unroll
    for (int i = 0; i < 4; i++) {
        int idx = tid + 128 * i;
        int row = idx >> 2, c4 = idx & 3;
        size_t aoff = (size_t)(bm + row) * GK + c * 32 + c4 * 8;
        CP16(buf + row * ASTRIDE + c4 * 16, Ahi + aoff);
        CP16(buf + ATILE + row * ASTRIDE + c4 * 16, Alo + aoff);
    }
#pragma unroll
    for (int i = 0; i < 4; i++) {
        int idx = tid + 128 * i;
        int row = idx >> 4, c16 = idx & 15;
        size_t boff = (size_t)(c * 32 + row) * N + bn + c16 * 8;
        CP16(buf + 2 * ATILE + row * BSTRIDE + c16 * 16, Bhi + boff);
        CP16(buf + 2 * ATILE + BTILE + row * BSTRIDE + c16 * 16, Blo + boff);
    }
}

template <int OUTMODE>
__global__ __launch_bounds__(128, 2) void gemm3_bf16_kernel(
    const __nv_bfloat16* __restrict__ Ahi, const __nv_bfloat16* __restrict__ Alo,
    const __nv_bfloat16* __restrict__ Bhi, const __nv_bfloat16* __restrict__ Blo,
    float* __restrict__ C,
    __nv_bfloat16* __restrict__ Chi, __nv_bfloat16* __restrict__ Clo, int N)
{
    extern __shared__ char gsm[];
    const uint32_t DATA = smem_u32(gsm);
    const int tid  = threadIdx.x;
    const int wid  = tid >> 5;
    const int lane = tid & 31;
    const int wm   = wid >> 1;
    const int wn   = wid & 1;
    const int bm = blockIdx.y * 128;
    const int bn = blockIdx.x * 128;

    float acc[4][8][4];
#pragma unroll
    for (int mt = 0; mt < 4; mt++)
#pragma unroll
        for (int nt = 0; nt < 8; nt++)
#pragma unroll
            for (int q = 0; q < 4; q++) acc[mt][nt][q] = 0.f;

    const int lr = lane & 15, lc = lane >> 4;

    gemm_issue(0, DATA, tid, bm, bn, N, Ahi, Alo, Bhi, Blo);
    CP_COMMIT();
    gemm_issue(1, DATA + BUFBYTES, tid, bm, bn, N, Ahi, Alo, Bhi, Blo);
    CP_COMMIT();

    const int NCHUNK = GK / 32;
    for (int c = 0; c < NCHUNK; c++) {
        if (c < NCHUNK - 1) { CP_WAIT1(); } else { CP_WAIT0(); }
        __syncthreads();
        if (c + 2 < NCHUNK) {
            gemm_issue(c + 2, DATA + (uint32_t)((c + 2) % GSTAGES) * BUFBYTES,
                       tid, bm, bn, N, Ahi, Alo, Bhi, Blo);
            CP_COMMIT();
        }

        const uint32_t cur = DATA + (uint32_t)(c % GSTAGES) * BUFBYTES;
#pragma unroll
        for (int ks = 0; ks < 2; ks++) {
            uint32_t ah[4][4], al[4][4], bh[4][4], bl[4][4];
#pragma unroll
            for (int mt = 0; mt < 4; mt++) {
                uint32_t aaddr = cur + (uint32_t)((wm * 64 + mt * 16 + lr) * ASTRIDE
                               + lc * 16 + ks * 32);
                LDSM4(ah[mt], aaddr);
                LDSM4(al[mt], aaddr + ATILE);
            }
#pragma unroll
            for (int np = 0; np < 4; np++) {
                uint32_t baddr = cur + 2 * ATILE
                               + (uint32_t)((ks * 16 + lr) * BSTRIDE
                               + wn * 128 + np * 32 + lc * 16);
                LDSM4T(bh[np], baddr);
                LDSM4T(bl[np], baddr + BTILE);
            }
#pragma unroll
            for (int mt = 0; mt < 4; mt++)
#pragma unroll
                for (int nt = 0; nt < 8; nt++)
                    MMA_BF16(acc[mt][nt], ah[mt],
                             bh[nt >> 1][(nt & 1) * 2], bh[nt >> 1][(nt & 1) * 2 + 1]);
#pragma unroll
            for (int mt = 0; mt < 4; mt++)
#pragma unroll
                for (int nt = 0; nt < 8; nt++)
                    MMA_BF16(acc[mt][nt], ah[mt],
                             bl[nt >> 1][(nt & 1) * 2], bl[nt >> 1][(nt & 1) * 2 + 1]);
#pragma unroll
            for (int mt = 0; mt < 4; mt++)
#pragma unroll
                for (int nt = 0; nt < 8; nt++)
                    MMA_BF16(acc[mt][nt], al[mt],
                             bh[nt >> 1][(nt & 1) * 2], bh[nt >> 1][(nt & 1) * 2 + 1]);
        }
    }

#pragma unroll
    for (int mt = 0; mt < 4; mt++) {
        int r0 = bm + wm * 64 + mt * 16 + (lane >> 2);
#pragma unroll
        for (int nt = 0; nt < 8; nt++) {
            int col = bn + wn * 64 + nt * 8 + (lane & 3) * 2;
            if (OUTMODE == 0) {
                *(float2*)(C + (size_t)r0 * N + col) =
                    make_float2(acc[mt][nt][0], acc[mt][nt][1]);
                *(float2*)(C + (size_t)(r0 + 8) * N + col) =
                    make_float2(acc[mt][nt][2], acc[mt][nt][3]);
            } else {
                // Pre-scale Q block (cols < Cc) by 1/8 — exact (power of 2),
                // replaces the per-kv-tile scale in the flash kernel.
                const float sc = (col < Cc) ? 0.125f : 1.0f;
#pragma unroll
                for (int rr = 0; rr < 2; rr++) {
                    float v0 = acc[mt][nt][rr * 2] * sc;
                    float v1 = acc[mt][nt][rr * 2 + 1] * sc;
                    __nv_bfloat162 hp = __floats2bfloat162_rn(v0, v1);
                    __nv_bfloat162 lp = __floats2bfloat162_rn(
                        v0 - __bfloat162float(__low2bfloat16(hp)),
                        v1 - __bfloat162float(__high2bfloat16(hp)));
                    size_t off = (size_t)(r0 + rr * 8) * N + col;
                    *(uint32_t*)(Chi + off) = *(uint32_t*)&hp;
                    *(uint32_t*)(Clo + off) = *(uint32_t*)&lp;
                }
            }
        }
    }
}

// ---------------------------------------------------------------------------
// Flash attention (3xBF16) — R13 config: 8 warps, 128-q CTA, 16 rows/warp,
// heavy-CTAs-first. Q arrives pre-scaled by 1/8, so no scale loop here.
// ---------------------------------------------------------------------------
#define FSTR   72
#define FTILE_B (64 * FSTR * 2)
#define FBUF_B  (4 * FTILE_B)
#define FSTAGES 3
#define FSMEM   (FSTAGES * FBUF_B)

__device__ __forceinline__ void flash_load_tile(
    uint32_t SB, int buf, int tid, int b, int h, int k0,
    const __nv_bfloat16* __restrict__ qkh, const __nv_bfloat16* __restrict__ qkl)
{
    const int row = tid >> 2;
    const int c0 = tid & 3;
    const size_t g = (size_t)(b * Tt + k0 + row) * (3 * Cc) + h * Dd;
    const __nv_bfloat16* s0 = qkh + g + Cc;
    const __nv_bfloat16* s1 = qkl + g + Cc;
    const __nv_bfloat16* s2 = qkh + g + 2 * Cc;
    const __nv_bfloat16* s3 = qkl + g + 2 * Cc;
    uint32_t d = SB + (uint32_t)buf * FBUF_B + (uint32_t)row * 144;
    CP16(d + 0 * FTILE_B + c0 * 16,       s0 + c0 * 8);
    CP16(d + 0 * FTILE_B + (c0 + 4) * 16, s0 + (c0 + 4) * 8);
    CP16(d + 1 * FTILE_B + c0 * 16,       s1 + c0 * 8);
    CP16(d + 1 * FTILE_B + (c0 + 4) * 16, s1 + (c0 + 4) * 8);
    CP16(d + 2 * FTILE_B + c0 * 16,       s2 + c0 * 8);
    CP16(d + 2 * FTILE_B + (c0 + 4) * 16, s2 + (c0 + 4) * 8);
    CP16(d + 3 * FTILE_B + c0 * 16,       s3 + c0 * 8);
    CP16(d + 3 * FTILE_B + (c0 + 4) * 16, s3 + (c0 + 4) * 8);
}

__global__ __launch_bounds__(256, 1) void flash_mma_kernel(
    const __nv_bfloat16* __restrict__ qkh, const __nv_bfloat16* __restrict__ qkl,
    __nv_bfloat16* __restrict__ ahi, __nv_bfloat16* __restrict__ alo)
{
    extern __shared__ char fsm[];
    const uint32_t SB = smem_u32(fsm);
    const int tid  = threadIdx.x;
    const int lane = tid & 31;
    const int wid  = tid >> 5;
    const int lr = lane >> 2;
    const int lq = lane & 3;
    const int qt = (int)(gridDim.x - 1 - blockIdx.x);   // heavy CTAs first
    const int h = blockIdx.y, b = blockIdx.z;
    const int q0 = qt * 128;
    const int RS = 3 * Cc;

    uint32_t qfh[4][4], qfl[4][4];
    {
        const __nv_bfloat16* qb = qkh + (size_t)(b * Tt + q0 + wid * 16) * RS + h * Dd;
        const __nv_bfloat16* ql = qkl + (size_t)(b * Tt + q0 + wid * 16) * RS + h * Dd;
#pragma unroll
        for (int s = 0; s < 4; s++) {
            int k = s * 16 + 2 * lq;
            qfh[s][0] = *(const uint32_t*)(qb + (size_t)lr * RS + k);
            qfh[s][1] = *(const uint32_t*)(qb + (size_t)(lr + 8) * RS + k);
            qfh[s][2] = *(const uint32_t*)(qb + (size_t)lr * RS + k + 8);
            qfh[s][3] = *(const uint32_t*)(qb + (size_t)(lr + 8) * RS + k + 8);
            qfl[s][0] = *(const uint32_t*)(ql + (size_t)lr * RS + k);
            qfl[s][1] = *(const uint32_t*)(ql + (size_t)(lr + 8) * RS + k);
            qfl[s][2] = *(const uint32_t*)(ql + (size_t)lr * RS + k + 8);
            qfl[s][3] = *(const uint32_t*)(ql + (size_t)(lr + 8) * RS + k + 8);
        }
    }

    float mA = -INFINITY, mB = -INFINITY, lA = 0.f, lB = 0.f;
    float o[8][4];
#pragma unroll
    for (int nt = 0; nt < 8; nt++)
#pragma unroll
        for (int q = 0; q < 4; q++) o[nt][q] = 0.f;

    const int ktmax = 2 * qt + 1;
    flash_load_tile(SB, 0, tid, b, h, 0, qkh, qkl);
    CP_COMMIT();
    flash_load_tile(SB, 1, tid, b, h, 64, qkh, qkl);
    CP_COMMIT();

    for (int kt = 0; kt <= ktmax; kt++) {
        if (kt < ktmax) { CP_WAIT1(); } else { CP_WAIT0(); }
        __syncthreads();
        if (kt + 2 <= ktmax) {
            flash_load_tile(SB, (kt + 2) % FSTAGES, tid, b, h, (kt + 2) * 64,
                            qkh, qkl);
            CP_COMMIT();
        }

        const int k0 = kt * 64;
        if (k0 <= q0 + wid * 16 + 15) {
            const uint32_t KB = SB + (uint32_t)(kt % FSTAGES) * FBUF_B;
            const uint32_t VB = KB + 2 * FTILE_B;

            float s[8][4];
#pragma unroll
            for (int nt = 0; nt < 8; nt++)
#pragma unroll
                for (int q = 0; q < 4; q++) s[nt][q] = 0.f;

#pragma unroll
            for (int sk = 0; sk < 4; sk++) {
                uint32_t bh[4][4], bl[4][4];
#pragma unroll
                for (int p = 0; p < 4; p++) {
                    uint32_t addr = KB
                        + (uint32_t)(((lane & 7) + ((lane >> 4) << 3) + p * 16) * 144
                        + ((lane >> 3) & 1) * 16 + sk * 32);
                    LDSM4(bh[p], addr);
                    LDSM4(bl[p], addr + FTILE_B);
                }
#pragma unroll
                for (int p = 0; p < 4; p++) {
                    MMA_BF16(s[2 * p],     qfh[sk], bh[p][0], bh[p][1]);
                    MMA_BF16(s[2 * p + 1], qfh[sk], bh[p][2], bh[p][3]);
                }
#pragma unroll
                for (int p = 0; p < 4; p++) {
                    MMA_BF16(s[2 * p],     qfh[sk], bl[p][0], bl[p][1]);
                    MMA_BF16(s[2 * p + 1], qfh[sk], bl[p][2], bl[p][3]);
                }
#pragma unroll
                for (int p = 0; p < 4; p++) {
                    MMA_BF16(s[2 * p],     qfl[sk], bh[p][0], bh[p][1]);
                    MMA_BF16(s[2 * p + 1], qfl[sk], bh[p][2], bh[p][3]);
                }
            }

            const int rowA = q0 + wid * 16 + lr;
            // (Q pre-scaled by 1/8 in the QKV epilogue — no scale loop here)

            if (k0 + 63 >= q0 + wid * 16) {
#pragma unroll
                for (int nt = 0; nt < 8; nt++) {
                    int col = k0 + nt * 8 + 2 * lq;
                    if (col     > rowA)     s[nt][0] = -INFINITY;
                    if (col + 1 > rowA)     s[nt][1] = -INFINITY;
                    if (col     > rowA + 8) s[nt][2] = -INFINITY;
                    if (col + 1 > rowA + 8) s[nt][3] = -INFINITY;
                }
            }

            float mxA = -INFINITY, mxB = -INFINITY;
#pragma unroll
            for (int nt = 0; nt < 8; nt++) {
                mxA = fmaxf(mxA, fmaxf(s[nt][0], s[nt][1]));
                mxB = fmaxf(mxB, fmaxf(s[nt][2], s[nt][3]));
            }
            mxA = fmaxf(mxA, __shfl_xor_sync(0xffffffffu, mxA, 1));
            mxA = fmaxf(mxA, __shfl_xor_sync(0xffffffffu, mxA, 2));
            mxB = fmaxf(mxB, __shfl_xor_sync(0xffffffffu, mxB, 1));
            mxB = fmaxf(mxB, __shfl_xor_sync(0xffffffffu, mxB, 2));
            float mnA = fmaxf(mA, mxA), mnB = fmaxf(mB, mxB);
            float alphaA = __expf(mA - mnA), alphaB = __expf(mB - mnB);
            mA = mnA; mB = mnB;

            float sumA = 0.f, sumB = 0.f;
#pragma unroll
            for (int nt = 0; nt < 8; nt++) {
                s[nt][0] = __expf(s[nt][0] - mnA);
                s[nt][1] = __expf(s[nt][1] - mnA);
                s[nt][2] = __expf(s[nt][2] - mnB);
                s[nt][3] = __expf(s[nt][3] - mnB);
                sumA += s[nt][0] + s[nt][1];
                sumB += s[nt][2] + s[nt][3];
            }
            sumA += __shfl_xor_sync(0xffffffffu, sumA, 1);
            sumA += __shfl_xor_sync(0xffffffffu, sumA, 2);
            sumB += __shfl_xor_sync(0xffffffffu, sumB, 1);
            sumB += __shfl_xor_sync(0xffffffffu, sumB, 2);
            lA = lA * alphaA + sumA;
            lB = lB * alphaB + sumB;

#pragma unroll
            for (int nt = 0; nt < 8; nt++) {
                o[nt][0] *= alphaA; o[nt][1] *= alphaA;
                o[nt][2] *= alphaB; o[nt][3] *= alphaB;
            }

#pragma unroll
            for (int sk = 0; sk < 4; sk++) {
                uint32_t ph[4], pl[4];
#pragma unroll
                for (int half = 0; half < 2; half++) {
                    const float* sv = s[2 * sk + half];
#pragma unroll
                    for (int rr = 0; rr < 2; rr++) {
                        float v0 = sv[rr * 2], v1 = sv[rr * 2 + 1];
                        __nv_bfloat162 hp = __floats2bfloat162_rn(v0, v1);
                        __nv_bfloat162 lp = __floats2bfloat162_rn(
                            v0 - __bfloat162float(__low2bfloat16(hp)),
                            v1 - __bfloat162float(__high2bfloat16(hp)));
                        ph[half * 2 + rr] = *(uint32_t*)&hp;
                        pl[half * 2 + rr] = *(uint32_t*)&lp;
                    }
                }
                uint32_t bh[4][4], bl[4][4];
#pragma unroll
                for (int p = 0; p < 4; p++) {
                    uint32_t addr = VB
                        + (uint32_t)((sk * 16 + (lane & 7) + (((lane >> 3) & 1) << 3)) * 144
                        + ((lane >> 4) * 16) + p * 32);
                    LDSM4T(bh[p], addr);
                    LDSM4T(bl[p], addr + FTILE_B);
                }
#pragma unroll
                for (int p = 0; p < 4; p++) {
                    MMA_BF16(o[2 * p],     ph, bh[p][0], bh[p][1]);
                    MMA_BF16(o[2 * p + 1], ph, bh[p][2], bh[p][3]);
                }
#pragma unroll
                for (int p = 0; p < 4; p++) {
                    MMA_BF16(o[2 * p],     ph, bl[p][0], bl[p][1]);
                    MMA_BF16(o[2 * p + 1], ph, bl[p][2], bl[p][3]);
                }
#pragma unroll
                for (int p = 0; p < 4; p++) {
                    MMA_BF16(o[2 * p],     pl, bh[p][0], bh[p][1]);
                    MMA_BF16(o[2 * p + 1], pl, bh[p][2], bh[p][3]);
                }
            }
        }
    }

    const float iA = 1.f / lA, iB = 1.f / lB;
    const size_t rA = (size_t)(b * Tt + q0 + wid * 16 + lr) * Cc + h * Dd;
    const size_t rB = rA + 8 * Cc;
#pragma unroll
    for (int nt = 0; nt < 8; nt++) {
        int col = nt * 8 + 2 * lq;
        float v0 = o[nt][0] * iA, v1 = o[nt][1] * iA;
        __nv_bfloat162 hp = __floats2bfloat162_rn(v0, v1);
        __nv_bfloat162 lp = __floats2bfloat162_rn(
            v0 - __bfloat162float(__low2bfloat16(hp)),
            v1 - __bfloat162float(__high2bfloat16(hp)));
        *(uint32_t*)(ahi + rA + col) = *(uint32_t*)&hp;
        *(uint32_t*)(alo + rA + col) = *(uint32_t*)&lp;
        float v2 = o[nt][2] * iB, v3 = o[nt][3] * iB;
        __nv_bfloat162 hp2 = __floats2bfloat162_rn(v2, v3);
        __nv_bfloat162 lp2 = __floats2bfloat162_rn(
            v2 - __bfloat162float(__low2bfloat16(hp2)),
            v3 - __bfloat162float(__high2bfloat16(hp2)));
        *(uint32_t*)(ahi + rB + col) = *(uint32_t*)&hp2;
        *(uint32_t*)(alo + rB + col) = *(uint32_t*)&lp2;
    }
}

// ---------------------------------------------------------------------------
// kernel_launch
// ---------------------------------------------------------------------------
extern "C" void kernel_launch(void* const* d_in, const int* in_sizes, int n_in,
                              void* d_out, int out_size)
{
    const float* x     = (const float*)d_in[0];
    const float* w_qkv = (const float*)d_in[1];
    const float* w_out = (const float*)d_in[2];
    float* out = (float*)d_out;

    __nv_bfloat16 *qkvhi, *qkvlo, *xhi, *xlo, *wqhi, *wqlo, *wohi, *wolo, *ahi, *alo;
    cudaGetSymbolAddress((void**)&qkvhi, g_qkvhi);
    cudaGetSymbolAddress((void**)&qkvlo, g_qkvlo);
    cudaGetSymbolAddress((void**)&xhi,  g_xhi);
    cudaGetSymbolAddress((void**)&xlo,  g_xlo);
    cudaGetSymbolAddress((void**)&wqhi, g_wqhi);
    cudaGetSymbolAddress((void**)&wqlo, g_wqlo);
    cudaGetSymbolAddress((void**)&wohi, g_wohi);
    cudaGetSymbolAddress((void**)&wolo, g_wolo);
    cudaGetSymbolAddress((void**)&ahi,  g_ahi);
    cudaGetSymbolAddress((void**)&alo,  g_alo);

    const int M = Bb * Tt;

    // 0) Fused split (one launch)
    {
        long long total = (long long)NX + NW + NO;
        int blocks = (int)(total / 1024);
        split3_kernel<<<blocks, 256>>>(x, w_qkv, w_out,
                                       xhi, xlo, wqhi, wqlo, wohi, wolo);
    }

    cudaFuncSetAttribute(gemm3_bf16_kernel<0>,
                         cudaFuncAttributeMaxDynamicSharedMemorySize, GSMEM);
    cudaFuncSetAttribute(gemm3_bf16_kernel<1>,
                         cudaFuncAttributeMaxDynamicSharedMemorySize, GSMEM);
    cudaFuncSetAttribute(flash_mma_kernel,
                         cudaFuncAttributeMaxDynamicSharedMemorySize, FSMEM);

    // 1) QKV projection (Q block pre-scaled by 1/8 in epilogue)
    gemm3_bf16_kernel<1><<<dim3(3 * Cc / 128, M / 128), 128, GSMEM>>>(
        xhi, xlo, wqhi, wqlo, nullptr, qkvhi, qkvlo, 3 * Cc);

    // 2) Causal flash attention
    flash_mma_kernel<<<dim3(Tt / 128, Hh, Bb), 256, FSMEM>>>(
        qkvhi, qkvlo, ahi, alo);

    // 3) Output projection
    gemm3_bf16_kernel<0><<<dim3(Cc / 128, M / 128), 128, GSMEM>>>(
        ahi, alo, wohi, wolo, out, nullptr, nullptr, Cc);
}

// round 16
// speedup vs baseline: 1.0793x; 1.0169x over previous
#include <cuda_runtime.h>
#include <cuda_bf16.h>
#include <math.h>
#include <stdint.h>

// Problem constants
#define Bb 4
#define Tt 2048
#define Hh 16
#define Dd 64
#define Cc 1024

// Scratch (__device__ globals per allocation rules)
__device__ __nv_bfloat16 g_qkvhi[Bb * Tt * 3 * Cc];
__device__ __nv_bfloat16 g_qkvlo[Bb * Tt * 3 * Cc];
__device__ __nv_bfloat16 g_xhi[Bb * Tt * Cc];
__device__ __nv_bfloat16 g_xlo[Bb * Tt * Cc];
__device__ __nv_bfloat16 g_wqhi[Cc * 3 * Cc];
__device__ __nv_bfloat16 g_wqlo[Cc * 3 * Cc];
__device__ __nv_bfloat16 g_wohi[Cc * Cc];
__device__ __nv_bfloat16 g_wolo[Cc * Cc];
__device__ __nv_bfloat16 g_ahi[Bb * Tt * Cc];
__device__ __nv_bfloat16 g_alo[Bb * Tt * Cc];

// ---------------------------------------------------------------------------
// PTX helpers
// ---------------------------------------------------------------------------
__device__ __forceinline__ uint32_t smem_u32(const void* p) {
    uint32_t a;
    asm("{ .reg .u64 t; cvta.to.shared.u64 t, %1; cvt.u32.u64 %0, t; }"
        : "=r"(a) : "l"(p));
    return a;
}

#define CP16(dst, src) \
    asm volatile("cp.async.cg.shared.global [%0], [%1], 16;" \
        :: "r"(dst), "l"(src) : "memory")
#define CP_COMMIT() asm volatile("cp.async.commit_group;" ::: "memory")
#define CP_WAIT1()  asm volatile("cp.async.wait_group 1;" ::: "memory")
#define CP_WAIT0()  asm volatile("cp.async.wait_group 0;" ::: "memory")

#define LDSM4(r, addr) \
    asm volatile("ldmatrix.sync.aligned.m8n8.x4.shared.b16 {%0,%1,%2,%3}, [%4];" \
        : "=r"((r)[0]), "=r"((r)[1]), "=r"((r)[2]), "=r"((r)[3]) : "r"(addr))
#define LDSM4T(r, addr) \
    asm volatile("ldmatrix.sync.aligned.m8n8.x4.trans.shared.b16 {%0,%1,%2,%3}, [%4];" \
        : "=r"((r)[0]), "=r"((r)[1]), "=r"((r)[2]), "=r"((r)[3]) : "r"(addr))

#define MMA_BF16(d, a, b0, b1) \
    asm volatile("mma.sync.aligned.m16n8k16.row.col.f32.bf16.bf16.f32 " \
        "{%0,%1,%2,%3}, {%4,%5,%6,%7}, {%8,%9}, {%0,%1,%2,%3};" \
        : "+f"((d)[0]), "+f"((d)[1]), "+f"((d)[2]), "+f"((d)[3]) \
        : "r"((a)[0]), "r"((a)[1]), "r"((a)[2]), "r"((a)[3]), "r"(b0), "r"(b1))

// ---------------------------------------------------------------------------
// Fused split: one launch covers x (8M), w_qkv (3M), w_out (1M) elements.
// ---------------------------------------------------------------------------
#define NX (Bb * Tt * Cc)
#define NW (Cc * 3 * Cc)
#define NO (Cc * Cc)

__global__ __launch_bounds__(256) void split3_kernel(
    const float* __restrict__ x, const float* __restrict__ wq,
    const float* __restrict__ wo,
    __nv_bfloat16* __restrict__ xhi, __nv_bfloat16* __restrict__ xlo,
    __nv_bfloat16* __restrict__ wqhi, __nv_bfloat16* __restrict__ wqlo,
    __nv_bfloat16* __restrict__ wohi, __nv_bfloat16* __restrict__ wolo)
{
    long long i = ((long long)blockIdx.x * 256 + threadIdx.x) * 4;
    const float* in;
    __nv_bfloat16 *hi, *lo;
    if (i < NX)                { in = x;  hi = xhi;  lo = xlo; }
    else if (i < NX + NW)      { in = wq; hi = wqhi; lo = wqlo; i -= NX; }
    else if (i < NX + NW + NO) { in = wo; hi = wohi; lo = wolo; i -= NX + NW; }
    else return;

    float4 v = *(const float4*)(in + i);
    __nv_bfloat16 h[4], l[4];
    float xx[4] = {v.x, v.y, v.z, v.w};
#pragma unroll
    for (int j = 0; j < 4; j++) {
        h[j] = __float2bfloat16(xx[j]);
        l[j] = __float2bfloat16(xx[j] - __bfloat162float(h[j]));
    }
    *(uint64_t*)(hi + i) = *(uint64_t*)h;
    *(uint64_t*)(lo + i) = *(uint64_t*)l;
}

// ---------------------------------------------------------------------------
// 3xBF16 split GEMM — R13 config + odd-parity chunk rotation (deskews the
// two co-resident CTAs' tensor/load phases; K-sum order change only).
// OUTMODE 1 pre-scales the Q block (cols < Cc) by 0.125*log2(e) so the flash
// kernel can use exp2f directly.
// ---------------------------------------------------------------------------
#define GK 1024
#define ASTRIDE 80
#define BSTRIDE 272
#define ATILE (128 * ASTRIDE)
#define BTILE (32 * BSTRIDE)
#define BUFBYTES (2 * ATILE + 2 * BTILE)
#define GSTAGES 3
#define GSMEM (GSTAGES * BUFBYTES)

#define QSCALE 0.18033688011112042f   // 0.125 * log2(e)

__device__ __forceinline__ void gemm_issue(
    int c, uint32_t buf, int tid, int bm, int bn, int N,
    const __nv_bfloat16* __restrict__ Ahi, const __nv_bfloat16* __restrict__ Alo,
    const __nv_bfloat16* __restrict__ Bhi, const __nv_bfloat16* __restrict__ Blo)
{
#pragma unroll
    for (int i = 0; i < 4; i++) {
        int idx = tid + 128 * i;
        int row = idx >> 2, c4 = idx & 3;
        size_t aoff = (size_t)(bm + row) * GK + c * 32 + c4 * 8;
        CP16(buf + row * ASTRIDE + c4 * 16, Ahi + aoff);
        CP16(buf + ATILE + row * ASTRIDE + c4 * 16, Alo + aoff);
    }
#pragma unroll
    for (int i = 0; i < 4; i++) {
        int idx = tid + 128 * i;
        int row = idx >> 4, c16 = idx & 15;
        size_t boff = (size_t)(c * 32 + row) * N + bn + c16 * 8;
        CP16(buf + 2 * ATILE + row * BSTRIDE + c16 * 16, Bhi + boff);
        CP16(buf + 2 * ATILE + BTILE + row * BSTRIDE + c16 * 16, Blo + boff);
    }
}

template <int OUTMODE>
__global__ __launch_bounds__(128, 2) void gemm3_bf16_kernel(
    const __nv_bfloat16* __restrict__ Ahi, const __nv_bfloat16* __restrict__ Alo,
    const __nv_bfloat16* __restrict__ Bhi, const __nv_bfloat16* __restrict__ Blo,
    float* __restrict__ C,
    __nv_bfloat16* __restrict__ Chi, __nv_bfloat16* __restrict__ Clo, int N)
{
    extern __shared__ char gsm[];
    const uint32_t DATA = smem_u32(gsm);
    const int tid  = threadIdx.x;
    const int wid  = tid >> 5;
    const int lane = tid & 31;
    const int wm   = wid >> 1;
    const int wn   = wid & 1;
    const int bm = blockIdx.y * 128;
    const int bn = blockIdx.x * 128;
    // Odd-parity CTAs process K-chunks rotated by half: deskews co-resident
    // CTAs' load/compute phases. Sum over all 32 chunks is unchanged.
    const int cofs = ((blockIdx.x ^ blockIdx.y) & 1) * 16;

    float acc[4][8][4];
#pragma unroll
    for (int mt = 0; mt < 4; mt++)
#pragma unroll
        for (int nt = 0; nt < 8; nt++)
#pragma unroll
            for (int q = 0; q < 4; q++) acc[mt][nt][q] = 0.f;

    const int lr = lane & 15, lc = lane >> 4;

    gemm_issue((0 + cofs) & 31, DATA, tid, bm, bn, N, Ahi, Alo, Bhi, Blo);
    CP_COMMIT();
    gemm_issue((1 + cofs) & 31, DATA + BUFBYTES, tid, bm, bn, N, Ahi, Alo, Bhi, Blo);
    CP_COMMIT();

    const int NCHUNK = GK / 32;
    for (int c = 0; c < NCHUNK; c++) {
        if (c < NCHUNK - 1) { CP_WAIT1(); } else { CP_WAIT0(); }
        __syncthreads();
        if (c + 2 < NCHUNK) {
            gemm_issue((c + 2 + cofs) & 31,
                       DATA + (uint32_t)((c + 2) % GSTAGES) * BUFBYTES,
                       tid, bm, bn, N, Ahi, Alo, Bhi, Blo);
            CP_COMMIT();
        }

        const uint32_t cur = DATA + (uint32_t)(c % GSTAGES) * BUFBYTES;
#pragma unroll
        for (int ks = 0; ks < 2; ks++) {
            uint32_t ah[4][4], al[4][4], bh[4][4], bl[4][4];
#pragma unroll
            for (int mt = 0; mt < 4; mt++) {
                uint32_t aaddr = cur + (uint32_t)((wm * 64 + mt * 16 + lr) * ASTRIDE
                               + lc * 16 + ks * 32);
                LDSM4(ah[mt], aaddr);
                LDSM4(al[mt], aaddr + ATILE);
            }
#pragma unroll
            for (int np = 0; np < 4; np++) {
                uint32_t baddr = cur + 2 * ATILE
                               + (uint32_t)((ks * 16 + lr) * BSTRIDE
                               + wn * 128 + np * 32 + lc * 16);
                LDSM4T(bh[np], baddr);
                LDSM4T(bl[np], baddr + BTILE);
            }
#pragma unroll
            for (int mt = 0; mt < 4; mt++)
#pragma unroll
                for (int nt = 0; nt < 8; nt++)
                    MMA_BF16(acc[mt][nt], ah[mt],
                             bh[nt >> 1][(nt & 1) * 2], bh[nt >> 1][(nt & 1) * 2 + 1]);
#pragma unroll
            for (int mt = 0; mt < 4; mt++)
#pragma unroll
                for (int nt = 0; nt < 8; nt++)
                    MMA_BF16(acc[mt][nt], ah[mt],
                             bl[nt >> 1][(nt & 1) * 2], bl[nt >> 1][(nt & 1) * 2 + 1]);
#pragma unroll
            for (int mt = 0; mt < 4; mt++)
#pragma unroll
                for (int nt = 0; nt < 8; nt++)
                    MMA_BF16(acc[mt][nt], al[mt],
                             bh[nt >> 1][(nt & 1) * 2], bh[nt >> 1][(nt & 1) * 2 + 1]);
        }
    }

#pragma unroll
    for (int mt = 0; mt < 4; mt++) {
        int r0 = bm + wm * 64 + mt * 16 + (lane >> 2);
#pragma unroll
        for (int nt = 0; nt < 8; nt++) {
            int col = bn + wn * 64 + nt * 8 + (lane & 3) * 2;
            if (OUTMODE == 0) {
                *(float2*)(C + (size_t)r0 * N + col) =
                    make_float2(acc[mt][nt][0], acc[mt][nt][1]);
                *(float2*)(C + (size_t)(r0 + 8) * N + col) =
                    make_float2(acc[mt][nt][2], acc[mt][nt][3]);
            } else {
                // Pre-scale Q block by 0.125*log2(e): folds both the attention
                // scale and the exp->exp2 conversion into the GEMM epilogue.
                const float sc = (col < Cc) ? QSCALE : 1.0f;
#pragma unroll
                for (int rr = 0; rr < 2; rr++) {
                    float v0 = acc[mt][nt][rr * 2] * sc;
                    float v1 = acc[mt][nt][rr * 2 + 1] * sc;
                    __nv_bfloat162 hp = __floats2bfloat162_rn(v0, v1);
                    __nv_bfloat162 lp = __floats2bfloat162_rn(
                        v0 - __bfloat162float(__low2bfloat16(hp)),
                        v1 - __bfloat162float(__high2bfloat16(hp)));
                    size_t off = (size_t)(r0 + rr * 8) * N + col;
                    *(uint32_t*)(Chi + off) = *(uint32_t*)&hp;
                    *(uint32_t*)(Clo + off) = *(uint32_t*)&lp;
                }
            }
        }
    }
}

// ---------------------------------------------------------------------------
// Flash attention (3xBF16) — R13 config; S lives in log2 domain (Q carries
// 0.125*log2e), softmax uses exp2f (one MUFU, no FMUL).
// ---------------------------------------------------------------------------
#define FSTR   72
#define FTILE_B (64 * FSTR * 2)
#define FBUF_B  (4 * FTILE_B)
#define FSTAGES 3
#define FSMEM   (FSTAGES * FBUF_B)

__device__ __forceinline__ void flash_load_tile(
    uint32_t SB, int buf, int tid, int b, int h, int k0,
    const __nv_bfloat16* __restrict__ qkh, const __nv_bfloat16* __restrict__ qkl)
{
    const int row = tid >> 2;
    const int c0 = tid & 3;
    const size_t g = (size_t)(b * Tt + k0 + row) * (3 * Cc) + h * Dd;
    const __nv_bfloat16* s0 = qkh + g + Cc;
    const __nv_bfloat16* s1 = qkl + g + Cc;
    const __nv_bfloat16* s2 = qkh + g + 2 * Cc;
    const __nv_bfloat16* s3 = qkl + g + 2 * Cc;
    uint32_t d = SB + (uint32_t)buf * FBUF_B + (uint32_t)row * 144;
    CP16(d + 0 * FTILE_B + c0 * 16,       s0 + c0 * 8);
    CP16(d + 0 * FTILE_B + (c0 + 4) * 16, s0 + (c0 + 4) * 8);
    CP16(d + 1 * FTILE_B + c0 * 16,       s1 + c0 * 8);
    CP16(d + 1 * FTILE_B + (c0 + 4) * 16, s1 + (c0 + 4) * 8);
    CP16(d + 2 * FTILE_B + c0 * 16,       s2 + c0 * 8);
    CP16(d + 2 * FTILE_B + (c0 + 4) * 16, s2 + (c0 + 4) * 8);
    CP16(d + 3 * FTILE_B + c0 * 16,       s3 + c0 * 8);
    CP16(d + 3 * FTILE_B + (c0 + 4) * 16, s3 + (c0 + 4) * 8);
}

__global__ __launch_bounds__(256, 1) void flash_mma_kernel(
    const __nv_bfloat16* __restrict__ qkh, const __nv_bfloat16* __restrict__ qkl,
    __nv_bfloat16* __restrict__ ahi, __nv_bfloat16* __restrict__ alo)
{
    extern __shared__ char fsm[];
    const uint32_t SB = smem_u32(fsm);
    const int tid  = threadIdx.x;
    const int lane = tid & 31;
    const int wid  = tid >> 5;
    const int lr = lane >> 2;
    const int lq = lane & 3;
    const int qt = (int)(gridDim.x - 1 - blockIdx.x);
    const int h = blockIdx.y, b = blockIdx.z;
    const int q0 = qt * 128;
    const int RS = 3 * Cc;

    uint32_t qfh[4][4], qfl[4][4];
    {
        const __nv_bfloat16* qb = qkh + (size_t)(b * Tt + q0 + wid * 16) * RS + h * Dd;
        const __nv_bfloat16* ql = qkl + (size_t)(b * Tt + q0 + wid * 16) * RS + h * Dd;
#pragma unroll
        for (int s = 0; s < 4; s++) {
            int k = s * 16 + 2 * lq;
            qfh[s][0] = *(const uint32_t*)(qb + (size_t)lr * RS + k);
            qfh[s][1] = *(const uint32_t*)(qb + (size_t)(lr + 8) * RS + k);
            qfh[s][2] = *(const uint32_t*)(qb + (size_t)lr * RS + k + 8);
            qfh[s][3] = *(const uint32_t*)(qb + (size_t)(lr + 8) * RS + k + 8);
            qfl[s][0] = *(const uint32_t*)(ql + (size_t)lr * RS + k);
            qfl[s][1] = *(const uint32_t*)(ql + (size_t)(lr + 8) * RS + k);
            qfl[s][2] = *(const uint32_t*)(ql + (size_t)lr * RS + k + 8);
            qfl[s][3] = *(const uint32_t*)(ql + (size_t)(lr + 8) * RS + k + 8);
        }
    }

    float mA = -INFINITY, mB = -INFINITY, lA = 0.f, lB = 0.f;
    float o[8][4];
#pragma unroll
    for (int nt = 0; nt < 8; nt++)
#pragma unroll
        for (int q = 0; q < 4; q++) o[nt][q] = 0.f;

    const int ktmax = 2 * qt + 1;
    flash_load_tile(SB, 0, tid, b, h, 0, qkh, qkl);
    CP_COMMIT();
    flash_load_tile(SB, 1, tid, b, h, 64, qkh, qkl);
    CP_COMMIT();

    for (int kt = 0; kt <= ktmax; kt++) {
        if (kt < ktmax) { CP_WAIT1(); } else { CP_WAIT0(); }
        __syncthreads();
        if (kt + 2 <= ktmax) {
            flash_load_tile(SB, (kt + 2) % FSTAGES, tid, b, h, (kt + 2) * 64,
                            qkh, qkl);
            CP_COMMIT();
        }

        const int k0 = kt * 64;
        if (k0 <= q0 + wid * 16 + 15) {
            const uint32_t KB = SB + (uint32_t)(kt % FSTAGES) * FBUF_B;
            const uint32_t VB = KB + 2 * FTILE_B;

            float s[8][4];
#pragma unroll
            for (int nt = 0; nt < 8; nt++)
#pragma unroll
                for (int q = 0; q < 4; q++) s[nt][q] = 0.f;

#pragma unroll
            for (int sk = 0; sk < 4; sk++) {
                uint32_t bh[4][4], bl[4][4];
#pragma unroll
                for (int p = 0; p < 4; p++) {
                    uint32_t addr = KB
                        + (uint32_t)(((lane & 7) + ((lane >> 4) << 3) + p * 16) * 144
                        + ((lane >> 3) & 1) * 16 + sk * 32);
                    LDSM4(bh[p], addr);
                    LDSM4(bl[p], addr + FTILE_B);
                }
#pragma unroll
                for (int p = 0; p < 4; p++) {
                    MMA_BF16(s[2 * p],     qfh[sk], bh[p][0], bh[p][1]);
                    MMA_BF16(s[2 * p + 1], qfh[sk], bh[p][2], bh[p][3]);
                }
#pragma unroll
                for (int p = 0; p < 4; p++) {
                    MMA_BF16(s[2 * p],     qfh[sk], bl[p][0], bl[p][1]);
                    MMA_BF16(s[2 * p + 1], qfh[sk], bl[p][2], bl[p][3]);
                }
#pragma unroll
                for (int p = 0; p < 4; p++) {
                    MMA_BF16(s[2 * p],     qfl[sk], bh[p][0], bh[p][1]);
                    MMA_BF16(s[2 * p + 1], qfl[sk], bh[p][2], bh[p][3]);
                }
            }

            const int rowA = q0 + wid * 16 + lr;
            // S is in log2 domain (Q pre-scaled by 0.125*log2e in QKV epilogue)

            if (k0 + 63 >= q0 + wid * 16) {
#pragma unroll
                for (int nt = 0; nt < 8; nt++) {
                    int col = k0 + nt * 8 + 2 * lq;
                    if (col     > rowA)     s[nt][0] = -INFINITY;
                    if (col + 1 > rowA)     s[nt][1] = -INFINITY;
                    if (col     > rowA + 8) s[nt][2] = -INFINITY;
                    if (col + 1 > rowA + 8) s[nt][3] = -INFINITY;
                }
            }

            float mxA = -INFINITY, mxB = -INFINITY;
#pragma unroll
            for (int nt = 0; nt < 8; nt++) {
                mxA = fmaxf(mxA, fmaxf(s[nt][0], s[nt][1]));
                mxB = fmaxf(mxB, fmaxf(s[nt][2], s[nt][3]));
            }
            mxA = fmaxf(mxA, __shfl_xor_sync(0xffffffffu, mxA, 1));
            mxA = fmaxf(mxA, __shfl_xor_sync(0xffffffffu, mxA, 2));
            mxB = fmaxf(mxB, __shfl_xor_sync(0xffffffffu, mxB, 1));
            mxB = fmaxf(mxB, __shfl_xor_sync(0xffffffffu, mxB, 2));
            float mnA = fmaxf(mA, mxA), mnB = fmaxf(mB, mxB);
            float alphaA = exp2f(mA - mnA), alphaB = exp2f(mB - mnB);
            mA = mnA; mB = mnB;

            float sumA = 0.f, sumB = 0.f;
#pragma unroll
            for (int nt = 0; nt < 8; nt++) {
                s[nt][0] = exp2f(s[nt][0] - mnA);
                s[nt][1] = exp2f(s[nt][1] - mnA);
                s[nt][2] = exp2f(s[nt][2] - mnB);
                s[nt][3] = exp2f(s[nt][3] - mnB);
                sumA += s[nt][0] + s[nt][1];
                sumB += s[nt][2] + s[nt][3];
            }
            sumA += __shfl_xor_sync(0xffffffffu, sumA, 1);
            sumA += __shfl_xor_sync(0xffffffffu, sumA, 2);
            sumB += __shfl_xor_sync(0xffffffffu, sumB, 1);
            sumB += __shfl_xor_sync(0xffffffffu, sumB, 2);
            lA = lA * alphaA + sumA;
            lB = lB * alphaB + sumB;

#pragma unroll
            for (int nt = 0; nt < 8; nt++) {
                o[nt][0] *= alphaA; o[nt][1] *= alphaA;
                o[nt][2] *= alphaB; o[nt][3] *= alphaB;
            }

#pragma unroll
            for (int sk = 0; sk < 4; sk++) {
                uint32_t ph[4], pl[4];
#pragma unroll
                for (int half = 0; half < 2; half++) {
                    const float* sv = s[2 * sk + half];
#pragma unroll
                    for (int rr = 0; rr < 2; rr++) {
                        float v0 = sv[rr * 2], v1 = sv[rr * 2 + 1];
                        __nv_bfloat162 hp = __floats2bfloat162_rn(v0, v1);
                        __nv_bfloat162 lp = __floats2bfloat162_rn(
                            v0 - __bfloat162float(__low2bfloat16(hp)),
                            v1 - __bfloat162float(__high2bfloat16(hp)));
                        ph[half * 2 + rr] = *(uint32_t*)&hp;
                        pl[half * 2 + rr] = *(uint32_t*)&lp;
                    }
                }
                uint32_t bh[4][4], bl[4][4];
#pragma unroll
                for (int p = 0; p < 4; p++) {
                    uint32_t addr = VB
                        + (uint32_t)((sk * 16 + (lane & 7) + (((lane >> 3) & 1) << 3)) * 144
                        + ((lane >> 4) * 16) + p * 32);
                    LDSM4T(bh[p], addr);
                    LDSM4T(bl[p], addr + FTILE_B);
                }
#pragma unroll
                for (int p = 0; p < 4; p++) {
                    MMA_BF16(o[2 * p],     ph, bh[p][0], bh[p][1]);
                    MMA_BF16(o[2 * p + 1], ph, bh[p][2], bh[p][3]);
                }
#pragma unroll
                for (int p = 0; p < 4; p++) {
                    MMA_BF16(o[2 * p],     ph, bl[p][0], bl[p][1]);
                    MMA_BF16(o[2 * p + 1], ph, bl[p][2], bl[p][3]);
                }
#pragma unroll
                for (int p = 0; p < 4; p++) {
                    MMA_BF16(o[2 * p],     pl, bh[p][0], bh[p][1]);
                    MMA_BF16(o[2 * p + 1], pl, bh[p][2], bh[p][3]);
                }
            }
        }
    }

    const float iA = 1.f / lA, iB = 1.f / lB;
    const size_t rA = (size_t)(b * Tt + q0 + wid * 16 + lr) * Cc + h * Dd;
    const size_t rB = rA + 8 * Cc;
#pragma unroll
    for (int nt = 0; nt < 8; nt++) {
        int col = nt * 8 + 2 * lq;
        float v0 = o[nt][0] * iA, v1 = o[nt][1] * iA;
        __nv_bfloat162 hp = __floats2bfloat162_rn(v0, v1);
        __nv_bfloat162 lp = __floats2bfloat162_rn(
            v0 - __bfloat162float(__low2bfloat16(hp)),
            v1 - __bfloat162float(__high2bfloat16(hp)));
        *(uint32_t*)(ahi + rA + col) = *(uint32_t*)&hp;
        *(uint32_t*)(alo + rA + col) = *(uint32_t*)&lp;
        float v2 = o[nt][2] * iB, v3 = o[nt][3] * iB;
        __nv_bfloat162 hp2 = __floats2bfloat162_rn(v2, v3);
        __nv_bfloat162 lp2 = __floats2bfloat162_rn(
            v2 - __bfloat162float(__low2bfloat16(hp2)),
            v3 - __bfloat162float(__high2bfloat16(hp2)));
        *(uint32_t*)(ahi + rB + col) = *(uint32_t*)&hp2;
        *(uint32_t*)(alo + rB + col) = *(uint32_t*)&lp2;
    }
}

// ---------------------------------------------------------------------------
// kernel_launch
// ---------------------------------------------------------------------------
extern "C" void kernel_launch(void* const* d_in, const int* in_sizes, int n_in,
                              void* d_out, int out_size)
{
    const float* x     = (const float*)d_in[0];
    const float* w_qkv = (const float*)d_in[1];
    const float* w_out = (const float*)d_in[2];
    float* out = (float*)d_out;

    __nv_bfloat16 *qkvhi, *qkvlo, *xhi, *xlo, *wqhi, *wqlo, *wohi, *wolo, *ahi, *alo;
    cudaGetSymbolAddress((void**)&qkvhi, g_qkvhi);
    cudaGetSymbolAddress((void**)&qkvlo, g_qkvlo);
    cudaGetSymbolAddress((void**)&xhi,  g_xhi);
    cudaGetSymbolAddress((void**)&xlo,  g_xlo);
    cudaGetSymbolAddress((void**)&wqhi, g_wqhi);
    cudaGetSymbolAddress((void**)&wqlo, g_wqlo);
    cudaGetSymbolAddress((void**)&wohi, g_wohi);
    cudaGetSymbolAddress((void**)&wolo, g_wolo);
    cudaGetSymbolAddress((void**)&ahi,  g_ahi);
    cudaGetSymbolAddress((void**)&alo,  g_alo);

    const int M = Bb * Tt;

    // 0) Fused split (one launch)
    {
        long long total = (long long)NX + NW + NO;
        int blocks = (int)(total / 1024);
        split3_kernel<<<blocks, 256>>>(x, w_qkv, w_out,
                                       xhi, xlo, wqhi, wqlo, wohi, wolo);
    }

    cudaFuncSetAttribute(gemm3_bf16_kernel<0>,
                         cudaFuncAttributeMaxDynamicSharedMemorySize, GSMEM);
    cudaFuncSetAttribute(gemm3_bf16_kernel<1>,
                         cudaFuncAttributeMaxDynamicSharedMemorySize, GSMEM);
    cudaFuncSetAttribute(flash_mma_kernel,
                         cudaFuncAttributeMaxDynamicSharedMemorySize, FSMEM);

    // 1) QKV projection (Q block pre-scaled by 0.125*log2e in epilogue)
    gemm3_bf16_kernel<1><<<dim3(3 * Cc / 128, M / 128), 128, GSMEM>>>(
        xhi, xlo, wqhi, wqlo, nullptr, qkvhi, qkvlo, 3 * Cc);

    // 2) Causal flash attention (exp2 domain softmax)
    flash_mma_kernel<<<dim3(Tt / 128, Hh, Bb), 256, FSMEM>>>(
        qkvhi, qkvlo, ahi, alo);

    // 3) Output projection
    gemm3_bf16_kernel<0><<<dim3(Cc / 128, M / 128), 128, GSMEM>>>(
        ahi, alo, wohi, wolo, out, nullptr, nullptr, Cc);
}